// round 1
// baseline (speedup 1.0000x reference)
#include <cuda_runtime.h>
#include <math.h>

#define H_ 192
#define W_ 192
#define C_ 256
#define C4_ 1024
#define N_ 36864
#define E_ 294912
#define K_ 289

// ---------------- scratch (static device globals; no allocation) ----------------
__device__ float g_img[(size_t)C_ * N_];   // channel-major image, carries residuals
__device__ float g_tb [(size_t)C_ * N_];   // temp
__device__ float g_t2 [(size_t)C_ * N_];   // temp
__device__ float g_big[(size_t)C4_ * N_];  // ffn2 hidden (4C x N)
__device__ float g_sig[(size_t)K_ * N_];   // signal (K x N) channel-major
__device__ float g_xn [(size_t)N_ * C_];   // node-major Xn for edge stage
__device__ float g_xa [(size_t)N_ * C_];   // node-major XA_sum / X_trans
__device__ float g_asum[N_];
__device__ float g_aij [E_];
__device__ float g_stats[2 * C4_];         // per-channel sum / sumsq
__device__ int   g_is64;

__device__ __forceinline__ float leaky(float x) { return x >= 0.f ? x : 0.01f * x; }

// ---------------- utility kernels ----------------
__global__ void k_zero(float* __restrict__ p, int n) {
    int i = blockIdx.x * blockDim.x + threadIdx.x;
    int stride = gridDim.x * blockDim.x;
    for (; i < n; i += stride) p[i] = 0.f;
}

__global__ void k_zero4(float4* __restrict__ p, int n4) {
    int i = blockIdx.x * blockDim.x + threadIdx.x;
    int stride = gridDim.x * blockDim.x;
    float4 z = make_float4(0.f, 0.f, 0.f, 0.f);
    for (; i < n4; i += stride) p[i] = z;
}

__global__ void k_leaky4(const float4* __restrict__ in, float4* __restrict__ out, int n4) {
    int i = blockIdx.x * blockDim.x + threadIdx.x;
    if (i >= n4) return;
    float4 v = in[i];
    v.x = leaky(v.x); v.y = leaky(v.y); v.z = leaky(v.z); v.w = leaky(v.w);
    out[i] = v;
}

// (N,C) row-major -> (C,N) channel-major
__global__ void k_nm2cm(const float* __restrict__ in, float* __restrict__ out) {
    __shared__ float tile[32][33];
    int nb = blockIdx.x * 32, cb = blockIdx.y * 32;
    int tx = threadIdx.x, ty = threadIdx.y;
#pragma unroll
    for (int i = 0; i < 32; i += 8)
        tile[ty + i][tx] = in[(size_t)(nb + ty + i) * C_ + cb + tx];
    __syncthreads();
#pragma unroll
    for (int i = 0; i < 32; i += 8)
        out[(size_t)(cb + ty + i) * N_ + nb + tx] = tile[tx][ty + i];
}

// (C,N) channel-major -> (N,C) row-major
__global__ void k_cm2nm(const float* __restrict__ in, float* __restrict__ out) {
    __shared__ float tile[32][33];
    int nb = blockIdx.x * 32, cb = blockIdx.y * 32;
    int tx = threadIdx.x, ty = threadIdx.y;
#pragma unroll
    for (int i = 0; i < 32; i += 8)
        tile[ty + i][tx] = in[(size_t)(cb + ty + i) * N_ + nb + tx];
    __syncthreads();
#pragma unroll
    for (int i = 0; i < 32; i += 8)
        out[(size_t)(nb + ty + i) * C_ + cb + tx] = tile[tx][ty + i];
}

// ---------------- batch-norm statistics & apply ----------------
// grid (Cn, parts), block 256. stats must be zeroed first.
__global__ void k_stats(const float* __restrict__ x) {
    int c = blockIdx.x;
    const float* xc = x + (size_t)c * N_;
    int tid = threadIdx.x;
    float s = 0.f, s2 = 0.f;
    for (int i = blockIdx.y * 256 + tid; i < N_; i += 256 * gridDim.y) {
        float v = xc[i];
        s += v; s2 += v * v;
    }
    __shared__ float sh[512];
    sh[tid] = s; sh[256 + tid] = s2;
    __syncthreads();
    for (int o = 128; o > 0; o >>= 1) {
        if (tid < o) { sh[tid] += sh[tid + o]; sh[256 + tid] += sh[256 + tid + o]; }
        __syncthreads();
    }
    if (tid == 0) {
        atomicAdd(&g_stats[2 * c], sh[0]);
        atomicAdd(&g_stats[2 * c + 1], sh[256]);
    }
}

// in-place bn on channel-major buffer. grid (N_/1024, C), block 256 (float4 per thread)
__global__ void k_bn(float* __restrict__ x, const float* __restrict__ gm, const float* __restrict__ bt) {
    int c = blockIdx.y;
    float m  = g_stats[2 * c] * (1.f / N_);
    float vr = g_stats[2 * c + 1] * (1.f / N_) - m * m;
    float rs = rsqrtf(vr + 1e-5f);
    float sc = rs * gm[c];
    float sb = bt[c] - m * sc;
    float4* p = reinterpret_cast<float4*>(x + (size_t)c * N_) + blockIdx.x * 256 + threadIdx.x;
    float4 v = *p;
    v.x = v.x * sc + sb; v.y = v.y * sc + sb; v.z = v.z * sc + sb; v.w = v.w * sc + sb;
    *p = v;
}

// img += bn(t). grid (N_/1024, C)
__global__ void k_bn_add(float* __restrict__ img, const float* __restrict__ t,
                         const float* __restrict__ gm, const float* __restrict__ bt) {
    int c = blockIdx.y;
    float m  = g_stats[2 * c] * (1.f / N_);
    float vr = g_stats[2 * c + 1] * (1.f / N_) - m * m;
    float rs = rsqrtf(vr + 1e-5f);
    float sc = rs * gm[c];
    float sb = bt[c] - m * sc;
    size_t off = (size_t)c * N_;
    int idx = blockIdx.x * 256 + threadIdx.x;
    float4* ip = reinterpret_cast<float4*>(img + off) + idx;
    const float4* tp = reinterpret_cast<const float4*>(t + off) + idx;
    float4 vi = *ip; float4 vt = *tp;
    vi.x += vt.x * sc + sb; vi.y += vt.y * sc + sb; vi.z += vt.z * sc + sb; vi.w += vt.w * sc + sb;
    *ip = vi;
}

// ---------------- depthwise 17x17 conv (pad 8) ----------------
// grid (36, C), block 256. L is leaky-preapplied channel-major input.
__global__ __launch_bounds__(256) void k_dw17(const float* __restrict__ L,
                                              const float* __restrict__ w0,
                                              float* __restrict__ out) {
    __shared__ float tile[48 * 49];
    __shared__ float ws[289];
    int c = blockIdx.y;
    int tb = blockIdx.x;
    int ty0 = (tb / 6) * 32, tx0 = (tb % 6) * 32;
    int tid = threadIdx.x;
    const float* Lc = L + (size_t)c * N_;
    for (int idx = tid; idx < 48 * 48; idx += 256) {
        int r = idx / 48, col = idx - r * 48;
        int gy = ty0 - 8 + r, gx = tx0 - 8 + col;
        float v = 0.f;
        if ((unsigned)gy < (unsigned)H_ && (unsigned)gx < (unsigned)W_) v = Lc[gy * W_ + gx];
        tile[r * 49 + col] = v;
    }
    for (int idx = tid; idx < 289; idx += 256) ws[idx] = w0[c * 289 + idx];
    __syncthreads();

    int oy = tid >> 3;
    int ox = (tid & 7) * 4;
    float a0 = 0.f, a1 = 0.f, a2 = 0.f, a3 = 0.f;
    for (int ky = 0; ky < 17; ky++) {
        const float* trow = &tile[(oy + ky) * 49 + ox];
        float row[20];
#pragma unroll
        for (int i = 0; i < 20; i++) row[i] = trow[i];
        const float* wr = &ws[ky * 17];
#pragma unroll
        for (int kx = 0; kx < 17; kx++) {
            float w = wr[kx];
            a0 += w * row[kx]; a1 += w * row[kx + 1]; a2 += w * row[kx + 2]; a3 += w * row[kx + 3];
        }
    }
    float* op = out + (size_t)c * N_ + (ty0 + oy) * W_ + tx0 + ox;
    op[0] = a0; op[1] = a1; op[2] = a2; op[3] = a3;
}

// ---------------- depthwise 3x3 conv, 4 outputs per input channel (pad 1) ----------------
// grid (36, C), block 256. out has 4C channels: oc = 4*c + j.
__global__ __launch_bounds__(256) void k_dw3(const float* __restrict__ L,
                                             const float* __restrict__ w,
                                             float* __restrict__ out) {
    __shared__ float tile[34 * 35];
    __shared__ float ws[36];
    int c = blockIdx.y;
    int tb = blockIdx.x;
    int ty0 = (tb / 6) * 32, tx0 = (tb % 6) * 32;
    int tid = threadIdx.x;
    const float* Lc = L + (size_t)c * N_;
    for (int idx = tid; idx < 34 * 34; idx += 256) {
        int r = idx / 34, col = idx - r * 34;
        int gy = ty0 - 1 + r, gx = tx0 - 1 + col;
        float v = 0.f;
        if ((unsigned)gy < (unsigned)H_ && (unsigned)gx < (unsigned)W_) v = Lc[gy * W_ + gx];
        tile[r * 35 + col] = v;
    }
    if (tid < 36) ws[tid] = w[c * 36 + tid];
    __syncthreads();

    int oy = tid >> 3;
    int ox = (tid & 7) * 4;
    float acc[4][4];
#pragma unroll
    for (int j = 0; j < 4; j++)
#pragma unroll
        for (int q = 0; q < 4; q++) acc[j][q] = 0.f;

    for (int ky = 0; ky < 3; ky++) {
        const float* trow = &tile[(oy + ky) * 35 + ox];
        float row[6];
#pragma unroll
        for (int i = 0; i < 6; i++) row[i] = trow[i];
#pragma unroll
        for (int kx = 0; kx < 3; kx++) {
#pragma unroll
            for (int j = 0; j < 4; j++) {
                float wv = ws[j * 9 + ky * 3 + kx];
                acc[j][0] += wv * row[kx];
                acc[j][1] += wv * row[kx + 1];
                acc[j][2] += wv * row[kx + 2];
                acc[j][3] += wv * row[kx + 3];
            }
        }
    }
    int p = (ty0 + oy) * W_ + tx0 + ox;
#pragma unroll
    for (int j = 0; j < 4; j++) {
        float* op = out + (size_t)(c * 4 + j) * N_ + p;
        op[0] = acc[j][0]; op[1] = acc[j][1]; op[2] = acc[j][2]; op[3] = acc[j][3];
    }
}

// ---------------- SIMT fp32 GEMM: Y(MxN_) = W(MxKc) * X(KcxN_) ----------------
// 128x128 block tile, BK=8, 8x8 micro-tile, double-buffered smem.
template<bool INLK, bool BIAS, bool OUTLK>
__global__ __launch_bounds__(256, 2)
void k_gemm(const float* __restrict__ Wm, const float* __restrict__ Xm,
            const float* __restrict__ bias, float* __restrict__ Ym,
            int M, int Kc) {
    __shared__ float As[2][8][128];
    __shared__ float Bs[2][8][128];
    const int bm = blockIdx.y * 128;
    const int bn = blockIdx.x * 128;
    const int tid = threadIdx.x;
    const int ar = tid >> 1;
    const int ak = (tid & 1) * 4;
    const int bk = tid >> 5;
    const int bq = (tid & 31) * 4;
    const int tr = tid >> 4;
    const int tc = tid & 15;

    float acc[8][8];
#pragma unroll
    for (int i = 0; i < 8; i++)
#pragma unroll
        for (int j = 0; j < 8; j++) acc[i][j] = 0.f;

    auto loadA = [&](int kt, int buf) {
        int row = bm + ar;
        float4 v = make_float4(0.f, 0.f, 0.f, 0.f);
        if (row < M) v = *reinterpret_cast<const float4*>(Wm + (size_t)row * Kc + kt + ak);
        As[buf][ak + 0][ar] = v.x;
        As[buf][ak + 1][ar] = v.y;
        As[buf][ak + 2][ar] = v.z;
        As[buf][ak + 3][ar] = v.w;
    };
    auto loadB = [&](int kt, int buf) {
        float4 v = *reinterpret_cast<const float4*>(Xm + (size_t)(kt + bk) * N_ + bn + bq);
        if (INLK) { v.x = leaky(v.x); v.y = leaky(v.y); v.z = leaky(v.z); v.w = leaky(v.w); }
        *reinterpret_cast<float4*>(&Bs[buf][bk][bq]) = v;
    };

    loadA(0, 0); loadB(0, 0);
    __syncthreads();
    const int nk = Kc >> 3;
    for (int t = 0; t < nk; t++) {
        int cur = t & 1, nxt = cur ^ 1;
        if (t + 1 < nk) { loadA((t + 1) << 3, nxt); loadB((t + 1) << 3, nxt); }
#pragma unroll
        for (int k = 0; k < 8; k++) {
            float4 a0 = *reinterpret_cast<const float4*>(&As[cur][k][tr * 8]);
            float4 a1 = *reinterpret_cast<const float4*>(&As[cur][k][tr * 8 + 4]);
            float4 b0 = *reinterpret_cast<const float4*>(&Bs[cur][k][tc * 8]);
            float4 b1 = *reinterpret_cast<const float4*>(&Bs[cur][k][tc * 8 + 4]);
            float av[8] = {a0.x, a0.y, a0.z, a0.w, a1.x, a1.y, a1.z, a1.w};
            float bv[8] = {b0.x, b0.y, b0.z, b0.w, b1.x, b1.y, b1.z, b1.w};
#pragma unroll
            for (int i = 0; i < 8; i++)
#pragma unroll
                for (int j = 0; j < 8; j++)
                    acc[i][j] += av[i] * bv[j];
        }
        __syncthreads();
    }
#pragma unroll
    for (int i = 0; i < 8; i++) {
        int row = bm + tr * 8 + i;
        if (row < M) {
            float bb = BIAS ? bias[row] : 0.f;
            float o[8];
#pragma unroll
            for (int j = 0; j < 8; j++) {
                float v = acc[i][j] + bb;
                if (OUTLK) v = leaky(v);
                o[j] = v;
            }
            float* yp = Ym + (size_t)row * N_ + bn + tc * 8;
            *reinterpret_cast<float4*>(yp)     = make_float4(o[0], o[1], o[2], o[3]);
            *reinterpret_cast<float4*>(yp + 4) = make_float4(o[4], o[5], o[6], o[7]);
        }
    }
}

// ---------------- edge stage ----------------
__global__ void k_detect(const int* __restrict__ info32) {
    if (blockIdx.x == 0 && threadIdx.x == 0) {
        long long s = 0;
        for (int i = 1; i < 256; i += 2) {
            int v = info32[i];
            s += (v < 0) ? -(long long)v : (long long)v;
        }
        g_is64 = (s == 0) ? 1 : 0;
    }
}

__device__ __forceinline__ void load_edge(const void* info, int e, int& src, int& k1, int& dst, int& k2) {
    if (g_is64) {
        const long long* q = reinterpret_cast<const long long*>(info) + (size_t)e * 4;
        src = (int)q[0]; k1 = (int)q[1]; dst = (int)q[2]; k2 = (int)q[3];
    } else {
        const int* q = reinterpret_cast<const int*>(info) + (size_t)e * 4;
        src = q[0]; k1 = q[1]; dst = q[2]; k2 = q[3];
    }
}

__global__ void k_edge1(const void* __restrict__ info, const float* __restrict__ msk) {
    int e = blockIdx.x * blockDim.x + threadIdx.x;
    if (e >= E_) return;
    int src, k1, dst, k2;
    load_edge(info, e, src, k1, dst, k2);
    float s = g_sig[(size_t)k1 * N_ + src] + g_sig[(size_t)k2 * N_ + dst];
    s = fminf(fmaxf(s, -5.f), 5.f);
    float a = expf(s) * msk[e];
    g_aij[e] = a;
    atomicAdd(&g_asum[dst], a);
}

__global__ void k_edge2(const void* __restrict__ info) {
    int w = (blockIdx.x * blockDim.x + threadIdx.x) >> 5;
    int lane = threadIdx.x & 31;
    if (w >= E_) return;
    int src, k1, dst, k2;
    load_edge(info, w, src, k1, dst, k2);
    float a = g_aij[w];
    const float* xs = g_xn + (size_t)src * C_;
    float* xd = g_xa + (size_t)dst * C_;
#pragma unroll
    for (int i = 0; i < 8; i++) {
        int c = lane + 32 * i;
        atomicAdd(&xd[c], xs[c] * a);
    }
}

// X_trans = XA/(Asum+1e-5) in place + per-channel stats. grid (8,64), block (32,8)
__global__ void k_xtrans_stats() {
    int c = blockIdx.x * 32 + threadIdx.x;
    int ty = threadIdx.y;
    float s = 0.f, s2 = 0.f;
    for (int n = blockIdx.y * 8 + ty; n < N_; n += gridDim.y * 8) {
        float d = g_asum[n] + 1e-5f;
        size_t idx = (size_t)n * C_ + c;
        float v = g_xa[idx] / d;
        g_xa[idx] = v;
        s += v; s2 += v * v;
    }
    __shared__ float sh[8][32], sh2[8][32];
    sh[ty][threadIdx.x] = s; sh2[ty][threadIdx.x] = s2;
    __syncthreads();
    if (ty == 0) {
#pragma unroll
        for (int i = 1; i < 8; i++) { s += sh[i][threadIdx.x]; s2 += sh2[i][threadIdx.x]; }
        atomicAdd(&g_stats[2 * c], s);
        atomicAdd(&g_stats[2 * c + 1], s2);
    }
}

// img(C,N) += bn1d(X_trans)(transposed from (N,C)). grid (1152,8), block (32,8)
__global__ void k_bn1d_add(const float* __restrict__ gm, const float* __restrict__ bt) {
    __shared__ float tile[32][33];
    int nb = blockIdx.x * 32, cb = blockIdx.y * 32;
    int tx = threadIdx.x, ty = threadIdx.y;
#pragma unroll
    for (int i = 0; i < 32; i += 8)
        tile[ty + i][tx] = g_xa[(size_t)(nb + ty + i) * C_ + cb + tx];
    __syncthreads();
#pragma unroll
    for (int i = 0; i < 32; i += 8) {
        int c = cb + ty + i;
        float m  = g_stats[2 * c] * (1.f / N_);
        float vr = g_stats[2 * c + 1] * (1.f / N_) - m * m;
        float rs = rsqrtf(vr + 1e-5f);
        float sc = rs * gm[c];
        float sb = bt[c] - m * sc;
        g_img[(size_t)c * N_ + nb + tx] += tile[tx][ty + i] * sc + sb;
    }
}

// out(N,C) = bn(t2)(C,N) + img(C,N), transposed. grid (1152,8), block (32,8)
__global__ void k_final(const float* __restrict__ gm, const float* __restrict__ bt,
                        float* __restrict__ out) {
    __shared__ float tile[32][33];
    int nb = blockIdx.x * 32, cb = blockIdx.y * 32;
    int tx = threadIdx.x, ty = threadIdx.y;
#pragma unroll
    for (int i = 0; i < 32; i += 8) {
        int c = cb + ty + i;
        float m  = g_stats[2 * c] * (1.f / N_);
        float vr = g_stats[2 * c + 1] * (1.f / N_) - m * m;
        float rs = rsqrtf(vr + 1e-5f);
        float sc = rs * gm[c];
        float sb = bt[c] - m * sc;
        size_t idx = (size_t)c * N_ + nb + tx;
        tile[ty + i][tx] = g_t2[idx] * sc + sb + g_img[idx];
    }
    __syncthreads();
#pragma unroll
    for (int i = 0; i < 32; i += 8)
        out[(size_t)(nb + ty + i) * C_ + cb + tx] = tile[tx][ty + i];
}

// ---------------- host orchestration ----------------
extern "C" void kernel_launch(void* const* d_in, const int* in_sizes, int n_in,
                              void* d_out, int out_size) {
    const float* X       = (const float*)d_in[0];
    const void*  info    = d_in[1];
    const float* msk     = (const float*)d_in[2];
    const float* ppm_w0  = (const float*)d_in[3];
    const float* ppm_g0  = (const float*)d_in[4];
    const float* ppm_b0  = (const float*)d_in[5];
    const float* ppm_w1  = (const float*)d_in[6];
    const float* ppm_g1  = (const float*)d_in[7];
    const float* ppm_b1  = (const float*)d_in[8];
    const float* ffn1_w0 = (const float*)d_in[9];
    const float* ffn1_g0 = (const float*)d_in[10];
    const float* ffn1_b0 = (const float*)d_in[11];
    const float* ffn1_w1 = (const float*)d_in[12];
    const float* ffn1_g1 = (const float*)d_in[13];
    const float* ffn1_b1 = (const float*)d_in[14];
    const float* dis_w1  = (const float*)d_in[15];
    const float* dis_b1  = (const float*)d_in[16];
    const float* dis_w2  = (const float*)d_in[17];
    const float* dis_b2  = (const float*)d_in[18];
    const float* bn_g    = (const float*)d_in[19];
    const float* bn_b    = (const float*)d_in[20];
    const float* ffn2_w0 = (const float*)d_in[21];
    const float* ffn2_g0 = (const float*)d_in[22];
    const float* ffn2_b0 = (const float*)d_in[23];
    const float* ffn2_w1 = (const float*)d_in[24];
    const float* ffn2_g1 = (const float*)d_in[25];
    const float* ffn2_b1 = (const float*)d_in[26];
    float* out = (float*)d_out;

    float *img, *tb, *t2, *big, *sig, *xn, *xa, *asum, *stats;
    cudaGetSymbolAddress((void**)&img,   g_img);
    cudaGetSymbolAddress((void**)&tb,    g_tb);
    cudaGetSymbolAddress((void**)&t2,    g_t2);
    cudaGetSymbolAddress((void**)&big,   g_big);
    cudaGetSymbolAddress((void**)&sig,   g_sig);
    cudaGetSymbolAddress((void**)&xn,    g_xn);
    cudaGetSymbolAddress((void**)&xa,    g_xa);
    cudaGetSymbolAddress((void**)&asum,  g_asum);
    cudaGetSymbolAddress((void**)&stats, g_stats);

    dim3 b32x8(32, 8);
    dim3 gT(N_ / 32, C_ / 32);           // transpose grid
    dim3 gDW(36, C_);                    // depthwise grids
    dim3 gDW4(36, C_);
    dim3 gBN(N_ / 1024, C_);             // bn apply, C channels
    dim3 gBN4(N_ / 1024, C4_);           // bn apply, 4C channels
    dim3 gStat(C_, 4);
    dim3 gStat4(C4_, 4);
    dim3 gG(N_ / 128, 2);                // GEMM M=256
    dim3 gGK(N_ / 128, 3);               // GEMM M=289
    const int n4 = C_ * N_ / 4;
    const int gE1 = (E_ + 255) / 256;

    k_detect<<<1, 32>>>((const int*)info);

    // ---- PPM block ----
    k_nm2cm<<<gT, b32x8>>>(X, img);
    k_leaky4<<<(n4 + 255) / 256, 256>>>((const float4*)img, (float4*)t2, n4);
    k_dw17<<<gDW, 256>>>(t2, ppm_w0, tb);
    k_zero<<<8, 256>>>(stats, 2 * C4_);
    k_stats<<<gStat, 256>>>(tb);
    k_bn<<<gBN, 256>>>(tb, ppm_g0, ppm_b0);
    k_gemm<true, false, false><<<gG, 256>>>(ppm_w1, tb, nullptr, t2, C_, C_);
    k_zero<<<8, 256>>>(stats, 2 * C4_);
    k_stats<<<gStat, 256>>>(t2);
    k_bn_add<<<gBN, 256>>>(img, t2, ppm_g1, ppm_b1);

    // ---- FFN1 block ----
    k_gemm<true, false, false><<<gG, 256>>>(ffn1_w0, img, nullptr, tb, C_, C_);
    k_zero<<<8, 256>>>(stats, 2 * C4_);
    k_stats<<<gStat, 256>>>(tb);
    k_bn<<<gBN, 256>>>(tb, ffn1_g0, ffn1_b0);
    k_gemm<true, false, false><<<gG, 256>>>(ffn1_w1, tb, nullptr, t2, C_, C_);
    k_zero<<<8, 256>>>(stats, 2 * C4_);
    k_stats<<<gStat, 256>>>(t2);
    k_bn_add<<<gBN, 256>>>(img, t2, ffn1_g1, ffn1_b1);

    // ---- discriminator / graph attention ----
    k_gemm<false, true, true><<<gG, 256>>>(dis_w1, img, dis_b1, tb, C_, C_);     // h = leaky(Xn@W1.T+b1)
    k_gemm<false, true, false><<<gGK, 256>>>(dis_w2, tb, dis_b2, sig, K_, C_);   // signal
    k_cm2nm<<<gT, b32x8>>>(img, xn);
    k_zero4<<<(N_ * C_ / 4 + 255) / 256, 256>>>((float4*)xa, N_ * C_ / 4);
    k_zero<<<(N_ + 255) / 256, 256>>>(asum, N_);
    k_edge1<<<gE1, 256>>>(info, msk);
    k_edge2<<<E_ / 8, 256>>>(info);
    k_zero<<<8, 256>>>(stats, 2 * C4_);
    k_xtrans_stats<<<dim3(8, 64), b32x8>>>();
    k_bn1d_add<<<gT, b32x8>>>(bn_g, bn_b);

    // ---- FFN2 block ----
    k_leaky4<<<(n4 + 255) / 256, 256>>>((const float4*)img, (float4*)tb, n4);
    k_dw3<<<gDW4, 256>>>(tb, ffn2_w0, big);
    k_zero<<<8, 256>>>(stats, 2 * C4_);
    k_stats<<<gStat4, 256>>>(big);
    k_bn<<<gBN4, 256>>>(big, ffn2_g0, ffn2_b0);
    k_gemm<true, false, false><<<gG, 256>>>(ffn2_w1, big, nullptr, t2, C_, C4_);
    k_zero<<<8, 256>>>(stats, 2 * C4_);
    k_stats<<<gStat, 256>>>(t2);
    k_final<<<gT, b32x8>>>(ffn2_g1, ffn2_b1, out);

    (void)in_sizes; (void)n_in; (void)out_size;
}

// round 3
// speedup vs baseline: 1.6726x; 1.6726x over previous
#include <cuda_runtime.h>
#include <cuda_bf16.h>
#include <cstdint>
#include <math.h>

#define H_ 192
#define W_ 192
#define C_ 256
#define C4_ 1024
#define N_ 36864
#define E_ 294912
#define K_ 289

// ======================= PTX helpers (base sm_103 target: NO tcgen05) ==========
__device__ __forceinline__ uint32_t smem_to_u32(const void* p) {
    uint32_t a;
    asm("{ .reg .u64 t; cvta.to.shared.u64 t, %1; cvt.u32.u64 %0, t; }" : "=r"(a) : "l"(p));
    return a;
}
__device__ __forceinline__ void cpa16(uint32_t dst, const void* src) {
    asm volatile("cp.async.cg.shared.global [%0], [%1], 16;" :: "r"(dst), "l"(src) : "memory");
}
__device__ __forceinline__ void cpa_commit() {
    asm volatile("cp.async.commit_group;" ::: "memory");
}
template<int NN>
__device__ __forceinline__ void cpa_wait() {
    asm volatile("cp.async.wait_group %0;" :: "n"(NN) : "memory");
}
__device__ __forceinline__ void ldm_x4(uint32_t* r, uint32_t addr) {
    asm volatile("ldmatrix.sync.aligned.m8n8.x4.shared.b16 {%0,%1,%2,%3}, [%4];"
        : "=r"(r[0]), "=r"(r[1]), "=r"(r[2]), "=r"(r[3]) : "r"(addr));
}
__device__ __forceinline__ void ldm_x2(uint32_t* r, uint32_t addr) {
    asm volatile("ldmatrix.sync.aligned.m8n8.x2.shared.b16 {%0,%1}, [%2];"
        : "=r"(r[0]), "=r"(r[1]) : "r"(addr));
}
__device__ __forceinline__ void mma_bf16(float* d, const uint32_t* a, const uint32_t* b) {
    asm volatile("mma.sync.aligned.m16n8k16.row.col.f32.bf16.bf16.f32 "
        "{%0,%1,%2,%3}, {%4,%5,%6,%7}, {%8,%9}, {%0,%1,%2,%3};"
        : "+f"(d[0]), "+f"(d[1]), "+f"(d[2]), "+f"(d[3])
        : "r"(a[0]), "r"(a[1]), "r"(a[2]), "r"(a[3]), "r"(b[0]), "r"(b[1]));
}
#define SWZ(o) ((o) ^ (((o) >> 3) & 0x70))

// ======================= scratch =======================
__device__ __align__(128) float g_img[(size_t)C_ * N_];
__device__ __align__(128) float g_tb [(size_t)C_ * N_];
__device__ __align__(128) float g_t2 [(size_t)C_ * N_];
__device__ __align__(128) float g_big[(size_t)C4_ * N_];
__device__ __align__(128) float g_sig[(size_t)K_ * N_];
__device__ __align__(128) float g_xn [(size_t)N_ * C_];
__device__ __align__(128) float g_xa [(size_t)N_ * C_];
__device__ __align__(128) float g_asum[N_];
__device__ __align__(128) float g_aij [E_];
__device__ __align__(128) float g_stats[2 * C4_];
__device__ int g_is64;
__device__ __align__(128) __nv_bfloat16 g_ahi[(size_t)N_ * C4_];
__device__ __align__(128) __nv_bfloat16 g_alo[(size_t)N_ * C4_];
#define WOFF_PPM1  0
#define WOFF_F1W0  65536
#define WOFF_F1W1  131072
#define WOFF_DIS1  196608
#define WOFF_DIS2  262144      /* 384x256 */
#define WOFF_F2W1  360448      /* 256x1024 */
#define WTOTAL     622592
__device__ __align__(128) __nv_bfloat16 g_whi[WTOTAL];
__device__ __align__(128) __nv_bfloat16 g_wlo[WTOTAL];

__device__ __forceinline__ float leaky(float x) { return x >= 0.f ? x : 0.01f * x; }

// ======================= utility kernels =======================
__global__ void k_zero(float* __restrict__ p, int n) {
    int i = blockIdx.x * blockDim.x + threadIdx.x;
    int stride = gridDim.x * blockDim.x;
    for (; i < n; i += stride) p[i] = 0.f;
}
__global__ void k_zero4(float4* __restrict__ p, int n4) {
    int i = blockIdx.x * blockDim.x + threadIdx.x;
    int stride = gridDim.x * blockDim.x;
    float4 z = make_float4(0.f, 0.f, 0.f, 0.f);
    for (; i < n4; i += stride) p[i] = z;
}
__global__ void k_nm2cm(const float* __restrict__ in, float* __restrict__ out) {
    __shared__ float tile[32][33];
    int nb = blockIdx.x * 32, cb = blockIdx.y * 32;
    int tx = threadIdx.x, ty = threadIdx.y;
#pragma unroll
    for (int i = 0; i < 32; i += 8)
        tile[ty + i][tx] = in[(size_t)(nb + ty + i) * C_ + cb + tx];
    __syncthreads();
#pragma unroll
    for (int i = 0; i < 32; i += 8)
        out[(size_t)(cb + ty + i) * N_ + nb + tx] = tile[tx][ty + i];
}

// ======================= BN stats & add =======================
__global__ void k_stats(const float* __restrict__ x) {
    int c = blockIdx.x;
    const float* xc = x + (size_t)c * N_;
    int tid = threadIdx.x;
    float s = 0.f, s2 = 0.f;
    for (int i = blockIdx.y * 256 + tid; i < N_; i += 256 * gridDim.y) {
        float v = xc[i];
        s += v; s2 += v * v;
    }
    __shared__ float sh[512];
    sh[tid] = s; sh[256 + tid] = s2;
    __syncthreads();
    for (int o = 128; o > 0; o >>= 1) {
        if (tid < o) { sh[tid] += sh[tid + o]; sh[256 + tid] += sh[256 + tid + o]; }
        __syncthreads();
    }
    if (tid == 0) {
        atomicAdd(&g_stats[2 * c], sh[0]);
        atomicAdd(&g_stats[2 * c + 1], sh[256]);
    }
}
__global__ void k_bn_add(float* __restrict__ img, const float* __restrict__ t,
                         const float* __restrict__ gm, const float* __restrict__ bt) {
    int c = blockIdx.y;
    float m  = g_stats[2 * c] * (1.f / N_);
    float vr = g_stats[2 * c + 1] * (1.f / N_) - m * m;
    float rs = rsqrtf(vr + 1e-5f);
    float sc = rs * gm[c];
    float sb = bt[c] - m * sc;
    size_t off = (size_t)c * N_;
    int idx = blockIdx.x * 256 + threadIdx.x;
    float4* ip = reinterpret_cast<float4*>(img + off) + idx;
    const float4* tp = reinterpret_cast<const float4*>(t + off) + idx;
    float4 vi = *ip; float4 vt = *tp;
    vi.x += vt.x * sc + sb; vi.y += vt.y * sc + sb; vi.z += vt.z * sc + sb; vi.w += vt.w * sc + sb;
    *ip = vi;
}

// ======================= split/transpose conversion =======================
// x: (Kc, N_) channel-major fp32 -> hi/lo: (N_, Kc) node-major bf16.
// flags: bit0 leaky (after bn), bit1 bn. xout optional fp32 (N_,Kc).
__global__ void k_split(const float* __restrict__ x, const float* __restrict__ gm,
                        const float* __restrict__ bt, __nv_bfloat16* __restrict__ hi,
                        __nv_bfloat16* __restrict__ lo, float* __restrict__ xout,
                        int Kc, int flags) {
    __shared__ float tile[64][33];
    int nb = blockIdx.x * 32, kb = blockIdx.y * 64;
    int tx = threadIdx.x, ty = threadIdx.y;
    bool do_lk = flags & 1, do_bn = flags & 2;
#pragma unroll
    for (int i = 0; i < 64; i += 8) {
        int k = kb + ty + i;
        float v = x[(size_t)k * N_ + nb + tx];
        if (do_bn) {
            float m  = g_stats[2 * k] * (1.f / N_);
            float vr = g_stats[2 * k + 1] * (1.f / N_) - m * m;
            float rs = rsqrtf(vr + 1e-5f);
            float sc = rs * gm[k];
            v = v * sc + bt[k] - m * sc;
        }
        if (do_lk) v = leaky(v);
        tile[ty + i][tx] = v;
    }
    __syncthreads();
#pragma unroll
    for (int i = 0; i < 32; i += 8) {
        int n = nb + ty + i;
        float v0 = tile[2 * tx][ty + i];
        float v1 = tile[2 * tx + 1][ty + i];
        __nv_bfloat16 h0 = __float2bfloat16(v0);
        __nv_bfloat16 h1 = __float2bfloat16(v1);
        __nv_bfloat16 l0 = __float2bfloat16(v0 - __bfloat162float(h0));
        __nv_bfloat16 l1 = __float2bfloat16(v1 - __bfloat162float(h1));
        size_t base = (size_t)n * Kc + kb;
        reinterpret_cast<__nv_bfloat162*>(hi + base)[tx] = __nv_bfloat162(h0, h1);
        reinterpret_cast<__nv_bfloat162*>(lo + base)[tx] = __nv_bfloat162(l0, l1);
        if (xout) reinterpret_cast<float2*>(xout + base)[tx] = make_float2(v0, v1);
    }
}
__global__ void k_wsplit(const float* __restrict__ w, __nv_bfloat16* __restrict__ hi,
                         __nv_bfloat16* __restrict__ lo, int M, int Mpad, int Kc) {
    int total = Mpad * Kc;
    for (int i = blockIdx.x * blockDim.x + threadIdx.x; i < total; i += gridDim.x * blockDim.x) {
        int r = i / Kc;
        float v = (r < M) ? w[i] : 0.f;
        __nv_bfloat16 h = __float2bfloat16(v);
        hi[i] = h;
        lo[i] = __float2bfloat16(v - __bfloat162float(h));
    }
}

// ======================= mma.sync bf16 GEMM (fp32 via hi/lo split) ============
// Y(M x N_) channel-major = W(Mpad x Kc) * A^T, A node-major (N_ x Kc).
// Block tile 128(M) x 128(N) x 32(K), 8 warps of 64x32. 2-stage cp.async pipeline.
// smem per stage 32KB: Wh@0, Wl@8K, Ah@16K, Al@24K. Swizzled: 2 rows per 128B.
#define GS_STAGE 32768
#define G_SMEM_TOTAL (2 * GS_STAGE + 1024)
__global__ __launch_bounds__(256)
void k_gemm_mma(const __nv_bfloat16* __restrict__ Whi, const __nv_bfloat16* __restrict__ Wlo,
                const __nv_bfloat16* __restrict__ Ahi, const __nv_bfloat16* __restrict__ Alo,
                const float* __restrict__ bias, float* __restrict__ Y,
                int M, int Kc, int BIAS, int OUTLK) {
    extern __shared__ char smem_raw[];
    uint32_t sb = (smem_to_u32(smem_raw) + 1023u) & ~1023u;
    __shared__ float sbias[128];

    const int tid = threadIdx.x;
    const int w = tid >> 5, L = tid & 31;
    const int n0 = blockIdx.x * 128;
    const int m0 = blockIdx.y * 128;
    const int m_off = (w & 1) * 64;
    const int n_off = (w >> 1) * 32;

    if (BIAS && tid < 128) sbias[tid] = bias[m0 + tid];

    // ldmatrix lane addresses (within-tile, swizzled)
    uint32_t aAddr, bAddr[4];
    {
        int r = m_off + (L & 15);
        uint32_t o = (uint32_t)((r >> 1) * 128 + (r & 1) * 64 + (L >> 4) * 16);
        aAddr = SWZ(o);
    }
#pragma unroll
    for (int nt = 0; nt < 4; nt++) {
        int r = n_off + nt * 8 + (L & 7);
        uint32_t o = (uint32_t)((r >> 1) * 128 + (r & 1) * 64 + ((L >> 3) & 1) * 16);
        bAddr[nt] = SWZ(o);
    }

    float acc[4][4][4];
#pragma unroll
    for (int i = 0; i < 4; i++)
#pragma unroll
        for (int j = 0; j < 4; j++)
#pragma unroll
            for (int q = 0; q < 4; q++) acc[i][j][q] = 0.f;

    const int nk = Kc >> 5;
    auto ldstage = [&](int t, int s) {
        uint32_t base = sb + s * GS_STAGE;
        int kc = t << 5;
#pragma unroll
        for (int i = 0; i < 2; i++) {
            int idx = tid + i * 256;
            int r = idx >> 2, c8 = idx & 3;
            uint32_t doff = SWZ((uint32_t)((r >> 1) * 128 + (r & 1) * 64 + c8 * 16));
            size_t goW = (size_t)(m0 + r) * Kc + kc + c8 * 8;
            size_t goA = (size_t)(n0 + r) * Kc + kc + c8 * 8;
            cpa16(base + doff,          Whi + goW);
            cpa16(base + 8192 + doff,   Wlo + goW);
            cpa16(base + 16384 + doff,  Ahi + goA);
            cpa16(base + 24576 + doff,  Alo + goA);
        }
        cpa_commit();
    };

    ldstage(0, 0);
    for (int t = 0; t < nk; t++) {
        if (t + 1 < nk) {
            ldstage(t + 1, (t + 1) & 1);
            cpa_wait<1>();
        } else {
            cpa_wait<0>();
        }
        __syncthreads();
        uint32_t stW = sb + (t & 1) * GS_STAGE;
        uint32_t stA = stW + 16384;
#pragma unroll
        for (int kk = 0; kk < 2; kk++) {
            uint32_t kx = kk ? 0x20u : 0u;
            uint32_t bh[4][2], bl[4][2];
#pragma unroll
            for (int nt = 0; nt < 4; nt++) {
                ldm_x2(bh[nt], (stA + bAddr[nt]) ^ kx);
                ldm_x2(bl[nt], (stA + 8192 + bAddr[nt]) ^ kx);
            }
#pragma unroll
            for (int mt = 0; mt < 4; mt++) {
                uint32_t ah[4], al[4];
                ldm_x4(ah, (stW + aAddr + mt * 1024) ^ kx);
                ldm_x4(al, (stW + 8192 + aAddr + mt * 1024) ^ kx);
#pragma unroll
                for (int nt = 0; nt < 4; nt++) {
                    mma_bf16(acc[mt][nt], ah, bh[nt]);
                    mma_bf16(acc[mt][nt], ah, bl[nt]);
                    mma_bf16(acc[mt][nt], al, bh[nt]);
                }
            }
        }
        __syncthreads();
    }

    // epilogue: acc tile (mt: m16, nt: n8). lane L: rows L/4 & L/4+8, cols 2*(L%4)+{0,1}
#pragma unroll
    for (int mt = 0; mt < 4; mt++) {
#pragma unroll
        for (int nt = 0; nt < 4; nt++) {
            int ocA = m0 + m_off + mt * 16 + (L >> 2);
            int n   = n0 + n_off + nt * 8 + 2 * (L & 3);
            float* d = acc[mt][nt];
            if (ocA < M) {
                float b0 = BIAS ? sbias[ocA - m0] : 0.f;
                float v0 = d[0] + b0, v1 = d[1] + b0;
                if (OUTLK) { v0 = leaky(v0); v1 = leaky(v1); }
                *reinterpret_cast<float2*>(Y + (size_t)ocA * N_ + n) = make_float2(v0, v1);
            }
            int ocB = ocA + 8;
            if (ocB < M) {
                float b1 = BIAS ? sbias[ocB - m0] : 0.f;
                float v2 = d[2] + b1, v3 = d[3] + b1;
                if (OUTLK) { v2 = leaky(v2); v3 = leaky(v3); }
                *reinterpret_cast<float2*>(Y + (size_t)ocB * N_ + n) = make_float2(v2, v3);
            }
        }
    }
}

// ======================= depthwise 17x17 (leaky fused) =======================
__global__ __launch_bounds__(256) void k_dw17(const float* __restrict__ L,
                                              const float* __restrict__ w0,
                                              float* __restrict__ out) {
    __shared__ float tile[48 * 81];
    __shared__ float ws[289];
    int c = blockIdx.y;
    int tb = blockIdx.x;
    int ty0 = (tb / 3) * 32, tx0 = (tb % 3) * 64;
    int tid = threadIdx.x;
    const float* Lc = L + (size_t)c * N_;
    for (int idx = tid; idx < 48 * 80; idx += 256) {
        int r = idx / 80, col = idx - r * 80;
        int gy = ty0 - 8 + r, gx = tx0 - 8 + col;
        float v = 0.f;
        if ((unsigned)gy < (unsigned)H_ && (unsigned)gx < (unsigned)W_) v = leaky(Lc[gy * W_ + gx]);
        tile[r * 81 + col] = v;
    }
    for (int idx = tid; idx < 289; idx += 256) ws[idx] = w0[c * 289 + idx];
    __syncthreads();

    int oy = tid >> 3;
    int ox = (tid & 7) * 8;
    float acc[8];
#pragma unroll
    for (int j = 0; j < 8; j++) acc[j] = 0.f;
    for (int ky = 0; ky < 17; ky++) {
        const float* trow = &tile[(oy + ky) * 81 + ox];
        float row[24];
#pragma unroll
        for (int i = 0; i < 24; i++) row[i] = trow[i];
        const float* wr = &ws[ky * 17];
#pragma unroll
        for (int kx = 0; kx < 17; kx++) {
            float w = wr[kx];
#pragma unroll
            for (int j = 0; j < 8; j++) acc[j] += w * row[kx + j];
        }
    }
    float* op = out + (size_t)c * N_ + (ty0 + oy) * W_ + tx0 + ox;
    *reinterpret_cast<float4*>(op)     = make_float4(acc[0], acc[1], acc[2], acc[3]);
    *reinterpret_cast<float4*>(op + 4) = make_float4(acc[4], acc[5], acc[6], acc[7]);
}

// ======================= depthwise 3x3 x4 (leaky fused) =======================
__global__ __launch_bounds__(256) void k_dw3(const float* __restrict__ L,
                                             const float* __restrict__ w,
                                             float* __restrict__ out) {
    __shared__ float tile[34 * 35];
    __shared__ float ws[36];
    int c = blockIdx.y;
    int tb = blockIdx.x;
    int ty0 = (tb / 6) * 32, tx0 = (tb % 6) * 32;
    int tid = threadIdx.x;
    const float* Lc = L + (size_t)c * N_;
    for (int idx = tid; idx < 34 * 34; idx += 256) {
        int r = idx / 34, col = idx - r * 34;
        int gy = ty0 - 1 + r, gx = tx0 - 1 + col;
        float v = 0.f;
        if ((unsigned)gy < (unsigned)H_ && (unsigned)gx < (unsigned)W_) v = leaky(Lc[gy * W_ + gx]);
        tile[r * 35 + col] = v;
    }
    if (tid < 36) ws[tid] = w[c * 36 + tid];
    __syncthreads();

    int oy = tid >> 3;
    int ox = (tid & 7) * 4;
    float acc[4][4];
#pragma unroll
    for (int j = 0; j < 4; j++)
#pragma unroll
        for (int q = 0; q < 4; q++) acc[j][q] = 0.f;
    for (int ky = 0; ky < 3; ky++) {
        const float* trow = &tile[(oy + ky) * 35 + ox];
        float row[6];
#pragma unroll
        for (int i = 0; i < 6; i++) row[i] = trow[i];
#pragma unroll
        for (int kx = 0; kx < 3; kx++) {
#pragma unroll
            for (int j = 0; j < 4; j++) {
                float wv = ws[j * 9 + ky * 3 + kx];
                acc[j][0] += wv * row[kx];
                acc[j][1] += wv * row[kx + 1];
                acc[j][2] += wv * row[kx + 2];
                acc[j][3] += wv * row[kx + 3];
            }
        }
    }
    int p = (ty0 + oy) * W_ + tx0 + ox;
#pragma unroll
    for (int j = 0; j < 4; j++) {
        float* op = out + (size_t)(c * 4 + j) * N_ + p;
        op[0] = acc[j][0]; op[1] = acc[j][1]; op[2] = acc[j][2]; op[3] = acc[j][3];
    }
}

// ======================= edge stage =======================
__global__ void k_detect(const int* __restrict__ info32) {
    if (blockIdx.x == 0 && threadIdx.x == 0) {
        long long s = 0;
        for (int i = 1; i < 256; i += 2) {
            int v = info32[i];
            s += (v < 0) ? -(long long)v : (long long)v;
        }
        g_is64 = (s == 0) ? 1 : 0;
    }
}
__device__ __forceinline__ void load_edge(const void* info, int e, int& src, int& k1, int& dst, int& k2) {
    if (g_is64) {
        const long long* q = reinterpret_cast<const long long*>(info) + (size_t)e * 4;
        src = (int)q[0]; k1 = (int)q[1]; dst = (int)q[2]; k2 = (int)q[3];
    } else {
        const int* q = reinterpret_cast<const int*>(info) + (size_t)e * 4;
        src = q[0]; k1 = q[1]; dst = q[2]; k2 = q[3];
    }
}
__global__ void k_edge1(const void* __restrict__ info, const float* __restrict__ msk) {
    int e = blockIdx.x * blockDim.x + threadIdx.x;
    if (e >= E_) return;
    int src, k1, dst, k2;
    load_edge(info, e, src, k1, dst, k2);
    float s = g_sig[(size_t)k1 * N_ + src] + g_sig[(size_t)k2 * N_ + dst];
    s = fminf(fmaxf(s, -5.f), 5.f);
    float a = expf(s) * msk[e];
    g_aij[e] = a;
    atomicAdd(&g_asum[dst], a);
}
__global__ void k_edge2(const void* __restrict__ info) {
    int w = (blockIdx.x * blockDim.x + threadIdx.x) >> 5;
    int lane = threadIdx.x & 31;
    if (w >= E_) return;
    int src, k1, dst, k2;
    load_edge(info, w, src, k1, dst, k2);
    float a = g_aij[w];
    const float* xs = g_xn + (size_t)src * C_;
    float* xd = g_xa + (size_t)dst * C_;
#pragma unroll
    for (int i = 0; i < 8; i++) {
        int c = lane + 32 * i;
        atomicAdd(&xd[c], xs[c] * a);
    }
}
__global__ void k_xtrans_stats() {
    int c = blockIdx.x * 32 + threadIdx.x;
    int ty = threadIdx.y;
    float s = 0.f, s2 = 0.f;
    for (int n = blockIdx.y * 8 + ty; n < N_; n += gridDim.y * 8) {
        float d = g_asum[n] + 1e-5f;
        size_t idx = (size_t)n * C_ + c;
        float v = g_xa[idx] / d;
        g_xa[idx] = v;
        s += v; s2 += v * v;
    }
    __shared__ float sh[8][32], sh2[8][32];
    sh[ty][threadIdx.x] = s; sh2[ty][threadIdx.x] = s2;
    __syncthreads();
    if (ty == 0) {
#pragma unroll
        for (int i = 1; i < 8; i++) { s += sh[i][threadIdx.x]; s2 += sh2[i][threadIdx.x]; }
        atomicAdd(&g_stats[2 * c], s);
        atomicAdd(&g_stats[2 * c + 1], s2);
    }
}
__global__ void k_bn1d_add(const float* __restrict__ gm, const float* __restrict__ bt) {
    __shared__ float tile[32][33];
    int nb = blockIdx.x * 32, cb = blockIdx.y * 32;
    int tx = threadIdx.x, ty = threadIdx.y;
#pragma unroll
    for (int i = 0; i < 32; i += 8)
        tile[ty + i][tx] = g_xa[(size_t)(nb + ty + i) * C_ + cb + tx];
    __syncthreads();
#pragma unroll
    for (int i = 0; i < 32; i += 8) {
        int c = cb + ty + i;
        float m  = g_stats[2 * c] * (1.f / N_);
        float vr = g_stats[2 * c + 1] * (1.f / N_) - m * m;
        float rs = rsqrtf(vr + 1e-5f);
        float sc = rs * gm[c];
        float sb = bt[c] - m * sc;
        g_img[(size_t)c * N_ + nb + tx] += tile[tx][ty + i] * sc + sb;
    }
}
__global__ void k_final(const float* __restrict__ gm, const float* __restrict__ bt,
                        float* __restrict__ out) {
    __shared__ float tile[32][33];
    int nb = blockIdx.x * 32, cb = blockIdx.y * 32;
    int tx = threadIdx.x, ty = threadIdx.y;
#pragma unroll
    for (int i = 0; i < 32; i += 8) {
        int c = cb + ty + i;
        float m  = g_stats[2 * c] * (1.f / N_);
        float vr = g_stats[2 * c + 1] * (1.f / N_) - m * m;
        float rs = rsqrtf(vr + 1e-5f);
        float sc = rs * gm[c];
        float sb = bt[c] - m * sc;
        size_t idx = (size_t)c * N_ + nb + tx;
        tile[ty + i][tx] = g_t2[idx] * sc + sb + g_img[idx];
    }
    __syncthreads();
#pragma unroll
    for (int i = 0; i < 32; i += 8)
        out[(size_t)(nb + ty + i) * C_ + cb + tx] = tile[tx][ty + i];
}

// ======================= host orchestration =======================
extern "C" void kernel_launch(void* const* d_in, const int* in_sizes, int n_in,
                              void* d_out, int out_size) {
    const float* X       = (const float*)d_in[0];
    const void*  info    = d_in[1];
    const float* msk     = (const float*)d_in[2];
    const float* ppm_w0  = (const float*)d_in[3];
    const float* ppm_g0  = (const float*)d_in[4];
    const float* ppm_b0  = (const float*)d_in[5];
    const float* ppm_w1  = (const float*)d_in[6];
    const float* ppm_g1  = (const float*)d_in[7];
    const float* ppm_b1  = (const float*)d_in[8];
    const float* ffn1_w0 = (const float*)d_in[9];
    const float* ffn1_g0 = (const float*)d_in[10];
    const float* ffn1_b0 = (const float*)d_in[11];
    const float* ffn1_w1 = (const float*)d_in[12];
    const float* ffn1_g1 = (const float*)d_in[13];
    const float* ffn1_b1 = (const float*)d_in[14];
    const float* dis_w1  = (const float*)d_in[15];
    const float* dis_b1  = (const float*)d_in[16];
    const float* dis_w2  = (const float*)d_in[17];
    const float* dis_b2  = (const float*)d_in[18];
    const float* bn_g    = (const float*)d_in[19];
    const float* bn_b    = (const float*)d_in[20];
    const float* ffn2_w0 = (const float*)d_in[21];
    const float* ffn2_g0 = (const float*)d_in[22];
    const float* ffn2_b0 = (const float*)d_in[23];
    const float* ffn2_w1 = (const float*)d_in[24];
    const float* ffn2_g1 = (const float*)d_in[25];
    const float* ffn2_b1 = (const float*)d_in[26];
    float* out = (float*)d_out;

    float *img, *tb, *t2, *big, *sig, *xn, *xa, *asum, *stats;
    __nv_bfloat16 *ahi, *alo, *whi, *wlo;
    cudaGetSymbolAddress((void**)&img,   g_img);
    cudaGetSymbolAddress((void**)&tb,    g_tb);
    cudaGetSymbolAddress((void**)&t2,    g_t2);
    cudaGetSymbolAddress((void**)&big,   g_big);
    cudaGetSymbolAddress((void**)&sig,   g_sig);
    cudaGetSymbolAddress((void**)&xn,    g_xn);
    cudaGetSymbolAddress((void**)&xa,    g_xa);
    cudaGetSymbolAddress((void**)&asum,  g_asum);
    cudaGetSymbolAddress((void**)&stats, g_stats);
    cudaGetSymbolAddress((void**)&ahi,   g_ahi);
    cudaGetSymbolAddress((void**)&alo,   g_alo);
    cudaGetSymbolAddress((void**)&whi,   g_whi);
    cudaGetSymbolAddress((void**)&wlo,   g_wlo);

    static bool attr_done = false;
    if (!attr_done) {
        cudaFuncSetAttribute(k_gemm_mma, cudaFuncAttributeMaxDynamicSharedMemorySize, G_SMEM_TOTAL);
        attr_done = true;
    }

    dim3 b32x8(32, 8);
    dim3 gT(N_ / 32, C_ / 32);
    dim3 gBN(N_ / 1024, C_);
    dim3 gStat(C_, 4);
    dim3 gStat4(C4_, 4);
    const int gE1 = (E_ + 255) / 256;

    auto split = [&](const float* x, const float* gm, const float* bt, float* xo, int Kc, int flags) {
        k_split<<<dim3(N_ / 32, Kc / 64), b32x8>>>(x, gm, bt, ahi, alo, xo, Kc, flags);
    };
    auto gemm = [&](int woff, const float* bias, float* Y, int M, int Mpad, int Kc, int BIAS, int OUTLK) {
        k_gemm_mma<<<dim3(N_ / 128, Mpad / 128), 256, G_SMEM_TOTAL>>>(
            whi + woff, wlo + woff, ahi, alo, bias, Y, M, Kc, BIAS, OUTLK);
    };

    k_detect<<<1, 32>>>((const int*)info);
    // weight conversions
    k_wsplit<<<64, 256>>>(ppm_w1,  whi + WOFF_PPM1, wlo + WOFF_PPM1, 256, 256, 256);
    k_wsplit<<<64, 256>>>(ffn1_w0, whi + WOFF_F1W0, wlo + WOFF_F1W0, 256, 256, 256);
    k_wsplit<<<64, 256>>>(ffn1_w1, whi + WOFF_F1W1, wlo + WOFF_F1W1, 256, 256, 256);
    k_wsplit<<<64, 256>>>(dis_w1,  whi + WOFF_DIS1, wlo + WOFF_DIS1, 256, 256, 256);
    k_wsplit<<<96, 256>>>(dis_w2,  whi + WOFF_DIS2, wlo + WOFF_DIS2, 289, 384, 256);
    k_wsplit<<<256, 256>>>(ffn2_w1, whi + WOFF_F2W1, wlo + WOFF_F2W1, 256, 256, 1024);

    // ---- PPM ----
    k_nm2cm<<<gT, b32x8>>>(X, img);
    k_dw17<<<dim3(18, C_), 256>>>(img, ppm_w0, tb);
    k_zero<<<8, 256>>>(stats, 2 * C4_);
    k_stats<<<gStat, 256>>>(tb);
    split(tb, ppm_g0, ppm_b0, nullptr, C_, 3);             // bn + leaky
    gemm(WOFF_PPM1, nullptr, t2, 256, 256, 256, 0, 0);
    k_zero<<<8, 256>>>(stats, 2 * C4_);
    k_stats<<<gStat, 256>>>(t2);
    k_bn_add<<<gBN, 256>>>(img, t2, ppm_g1, ppm_b1);

    // ---- FFN1 ----
    split(img, nullptr, nullptr, nullptr, C_, 1);          // leaky only
    gemm(WOFF_F1W0, nullptr, tb, 256, 256, 256, 0, 0);
    k_zero<<<8, 256>>>(stats, 2 * C4_);
    k_stats<<<gStat, 256>>>(tb);
    split(tb, ffn1_g0, ffn1_b0, nullptr, C_, 3);           // bn + leaky
    gemm(WOFF_F1W1, nullptr, t2, 256, 256, 256, 0, 0);
    k_zero<<<8, 256>>>(stats, 2 * C4_);
    k_stats<<<gStat, 256>>>(t2);
    k_bn_add<<<gBN, 256>>>(img, t2, ffn1_g1, ffn1_b1);

    // ---- discriminator / graph attention ----
    split(img, nullptr, nullptr, xn, C_, 0);               // raw Xn + split
    gemm(WOFF_DIS1, dis_b1, tb, 256, 256, 256, 1, 1);      // h = leaky(Xn W1^T + b1)
    split(tb, nullptr, nullptr, nullptr, C_, 0);
    gemm(WOFF_DIS2, dis_b2, sig, 289, 384, 256, 1, 0);     // signal
    k_zero4<<<(N_ * C_ / 4 + 255) / 256, 256>>>((float4*)xa, N_ * C_ / 4);
    k_zero<<<(N_ + 255) / 256, 256>>>(asum, N_);
    k_edge1<<<gE1, 256>>>(info, msk);
    k_edge2<<<E_ / 8, 256>>>(info);
    k_zero<<<8, 256>>>(stats, 2 * C4_);
    k_xtrans_stats<<<dim3(8, 64), b32x8>>>();
    k_bn1d_add<<<gT, b32x8>>>(bn_g, bn_b);

    // ---- FFN2 ----
    k_dw3<<<dim3(36, C_), 256>>>(img, ffn2_w0, big);       // leaky fused
    k_zero<<<8, 256>>>(stats, 2 * C4_);
    k_stats<<<gStat4, 256>>>(big);
    split(big, ffn2_g0, ffn2_b0, nullptr, C4_, 3);         // bn + leaky
    gemm(WOFF_F2W1, nullptr, t2, 256, 256, 1024, 0, 0);
    k_zero<<<8, 256>>>(stats, 2 * C4_);
    k_stats<<<gStat, 256>>>(t2);
    k_final<<<gT, b32x8>>>(ffn2_g1, ffn2_b1, out);

    (void)in_sizes; (void)n_in; (void)out_size;
}